// round 12
// baseline (speedup 1.0000x reference)
#include <cuda_runtime.h>

// KBestDetector: B=16384, M=16 rx, S=8 streams, 16-QAM (NBPS=4), K=64.
// WARP-PER-BATCH, CTA = 2 warps. No __syncthreads; warp-synchronous.
//
// FROZEN (round-10 lesson): chol16 / chol8 / column norms keep round-9's
// exact summation order — the argsort and K-best tree are discretely
// sensitive to preamble rounding.
//
// Round-12 change (bit-exact schedule transform): full layers keep parent
// tables in REGISTERS (lane owns parents 2*lane, 2*lane+1); classification,
// re-histogram, and compaction are unrolled-32 predicated register code;
// compaction slots via popc-prefix (same order as the old serial cursor).
// Layer 6 (16 parents, cross-lane sharing) keeps the shared-memory path.

#define FULLM 0xffffffffu
#define WPB 2
#define PHASE_BYTES 3584

#define MIN4_(pa, B) fminf(fminf((pa) + (B).x, (pa) + (B).y), fminf((pa) + (B).z, (pa) + (B).w))

template<bool FULL_L>
__device__ __forceinline__ void layer_step(
    int l, int cur, int lane,
    float2 (*CshW)[8], float2* YbarW, float2* PtsW,
    float (*CdistW)[64], unsigned (*CsymW)[64],
    float (*PrsW)[4], float (*PisW)[4],
    unsigned* HistW, unsigned long long* EqKW)
{
    const int nxt = cur ^ 1;
    const int shl = 4 * l;
    float4 A0, B0, A1, B1;
    unsigned psym0 = 0u, psym1 = 0u;
    float pa0 = 0.f, pa1 = 0.f;

    // ---- parent separable tables (expressions identical to round 11) ----
    if (FULL_L) {
        #pragma unroll
        for (int h = 0; h < 2; h++) {
            int p = 2*lane + h;
            unsigned sym = CsymW[cur][p];
            float pd = CdistW[cur][p];
            float ir = 0.f, ii = 0.f;
            #pragma unroll 1
            for (int j = l + 1; j < 8; j++) {
                int q = (sym >> (4*j)) & 15;
                float2 c = CshW[j][l];
                float2 pt = PtsW[q];
                ir += c.x*pt.x + c.y*pt.y;
                ii += c.x*pt.y - c.y*pt.x;
            }
            float br = YbarW[l].x - ir;
            float bi = YbarW[l].y - ii;
            float rll = CshW[l][l].x;
            float4 prv, piv;
            {
                float t0 = fmaf(-rll, PtsW[0].x,  br);
                float t1 = fmaf(-rll, PtsW[2].x,  br);
                float t2 = fmaf(-rll, PtsW[8].x,  br);
                float t3 = fmaf(-rll, PtsW[10].x, br);
                prv.x = fmaf(t0, t0, pd); prv.y = fmaf(t1, t1, pd);
                prv.z = fmaf(t2, t2, pd); prv.w = fmaf(t3, t3, pd);
            }
            {
                float t0 = fmaf(-rll, PtsW[0].y, bi);
                float t1 = fmaf(-rll, PtsW[1].y, bi);
                float t2 = fmaf(-rll, PtsW[4].y, bi);
                float t3 = fmaf(-rll, PtsW[5].y, bi);
                piv.x = t0*t0; piv.y = t1*t1; piv.z = t2*t2; piv.w = t3*t3;
            }
            if (h == 0) { A0 = prv; B0 = piv; psym0 = sym; }
            else        { A1 = prv; B1 = piv; psym1 = sym; }
        }
    } else {
        if (lane < 16) {
            unsigned sym = CsymW[cur][lane];
            float pd = CdistW[cur][lane];
            float ir = 0.f, ii = 0.f;
            #pragma unroll 1
            for (int j = l + 1; j < 8; j++) {
                int q = (sym >> (4*j)) & 15;
                float2 c = CshW[j][l];
                float2 pt = PtsW[q];
                ir += c.x*pt.x + c.y*pt.y;
                ii += c.x*pt.y - c.y*pt.x;
            }
            float br = YbarW[l].x - ir;
            float bi = YbarW[l].y - ii;
            float rll = CshW[l][l].x;
            float4 prv, piv;
            {
                float t0 = fmaf(-rll, PtsW[0].x,  br);
                float t1 = fmaf(-rll, PtsW[2].x,  br);
                float t2 = fmaf(-rll, PtsW[8].x,  br);
                float t3 = fmaf(-rll, PtsW[10].x, br);
                prv.x = fmaf(t0, t0, pd); prv.y = fmaf(t1, t1, pd);
                prv.z = fmaf(t2, t2, pd); prv.w = fmaf(t3, t3, pd);
            }
            {
                float t0 = fmaf(-rll, PtsW[0].y, bi);
                float t1 = fmaf(-rll, PtsW[1].y, bi);
                float t2 = fmaf(-rll, PtsW[4].y, bi);
                float t3 = fmaf(-rll, PtsW[5].y, bi);
                piv.x = t0*t0; piv.y = t1*t1; piv.z = t2*t2; piv.w = t3*t3;
            }
            *(float4*)PrsW[lane] = prv;
            *(float4*)PisW[lane] = piv;
        }
    }
    *(uint4*)&HistW[lane*4] = make_uint4(0u, 0u, 0u, 0u);
    __syncwarp();

    // ---- pass 1: per-lane min + certificate payload ----
    float mn, Tpay;
    if (FULL_L) {
        float m0 = fminf(fminf(MIN4_(A0.x, B0), MIN4_(A0.y, B0)),
                         fminf(MIN4_(A0.z, B0), MIN4_(A0.w, B0)));
        float m1 = fminf(fminf(MIN4_(A1.x, B1), MIN4_(A1.y, B1)),
                         fminf(MIN4_(A1.z, B1), MIN4_(A1.w, B1)));
        mn   = fminf(m0, m1);
        Tpay = fmaxf(m0, m1);          // parent-best: certifies d_(64)
    } else {
        A0 = *(const float4*)PrsW[lane >> 1];
        B0 = *(const float4*)PisW[lane >> 1];
        psym0 = CsymW[cur][lane >> 1];
        pa0 = (lane & 1) ? A0.z : A0.x;
        pa1 = (lane & 1) ? A0.w : A0.y;
        float d0 = pa0 + B0.x, d1 = pa0 + B0.y, d2 = pa1 + B0.x, d3 = pa1 + B0.y;
        float d4 = pa0 + B0.z, d5 = pa0 + B0.w, d6 = pa1 + B0.z, d7 = pa1 + B0.w;
        mn   = fminf(fminf(fminf(d0,d1),fminf(d2,d3)), fminf(fminf(d4,d5),fminf(d6,d7)));
        Tpay = fmaxf(fmaxf(fmaxf(d0,d1),fmaxf(d2,d3)), fmaxf(fmaxf(d4,d5),fmaxf(d6,d7)));
    }
    float lo = mn, T = Tpay;
    #pragma unroll
    for (int o = 16; o; o >>= 1) {
        lo = fminf(lo, __shfl_xor_sync(FULLM, lo, o));
        T  = fmaxf(T,  __shfl_xor_sync(FULLM, T,  o));
    }
    float hi = T;
    float scale = 128.f / fmaxf(hi - lo, 1e-30f);

    // ---- pass 2: prune (d<=T) + level-0 histogram + active mask ----
    unsigned actm = 0u, selm = 0u;
    #define P2_(k, pa, pb) { float d = (pa) + (pb); \
        if (d <= T) { int bn = (int)((d - lo) * scale); \
            bn = bn > 127 ? 127 : bn; \
            atomicAdd(&HistW[bn], 1u); actm |= (1u << (k)); } }
    if (FULL_L) {
        P2_( 0, A0.x, B0.x) P2_( 1, A0.x, B0.y) P2_( 2, A0.y, B0.x) P2_( 3, A0.y, B0.y)
        P2_( 4, A0.x, B0.z) P2_( 5, A0.x, B0.w) P2_( 6, A0.y, B0.z) P2_( 7, A0.y, B0.w)
        P2_( 8, A0.z, B0.x) P2_( 9, A0.z, B0.y) P2_(10, A0.w, B0.x) P2_(11, A0.w, B0.y)
        P2_(12, A0.z, B0.z) P2_(13, A0.z, B0.w) P2_(14, A0.w, B0.z) P2_(15, A0.w, B0.w)
        P2_(16, A1.x, B1.x) P2_(17, A1.x, B1.y) P2_(18, A1.y, B1.x) P2_(19, A1.y, B1.y)
        P2_(20, A1.x, B1.z) P2_(21, A1.x, B1.w) P2_(22, A1.y, B1.z) P2_(23, A1.y, B1.w)
        P2_(24, A1.z, B1.x) P2_(25, A1.z, B1.y) P2_(26, A1.w, B1.x) P2_(27, A1.w, B1.y)
        P2_(28, A1.z, B1.z) P2_(29, A1.z, B1.w) P2_(30, A1.w, B1.z) P2_(31, A1.w, B1.w)
    } else {
        P2_(0, pa0, B0.x) P2_(1, pa0, B0.y) P2_(2, pa1, B0.x) P2_(3, pa1, B0.y)
        P2_(4, pa0, B0.z) P2_(5, pa0, B0.w) P2_(6, pa1, B0.z) P2_(7, pa1, B0.w)
    }
    #undef P2_

    // ---- adaptive select loop (exact; ties via EqK) ----
    int c_sel = 0;
    #pragma unroll 1
    for (int lev = 0; ; lev++) {
        if (lev) {
            __syncwarp();
            *(uint4*)&HistW[lane*4] = make_uint4(0u, 0u, 0u, 0u);
            __syncwarp();
            scale = 128.f / fmaxf(hi - lo, 1e-30f);
            #define H2_(k, pa, pb) if ((actm >> (k)) & 1u) { \
                float d = (pa) + (pb); \
                int bn = (int)((d - lo) * scale); \
                bn = bn < 0 ? 0 : (bn > 127 ? 127 : bn); \
                atomicAdd(&HistW[bn], 1u); }
            if (FULL_L) {
                H2_( 0, A0.x, B0.x) H2_( 1, A0.x, B0.y) H2_( 2, A0.y, B0.x) H2_( 3, A0.y, B0.y)
                H2_( 4, A0.x, B0.z) H2_( 5, A0.x, B0.w) H2_( 6, A0.y, B0.z) H2_( 7, A0.y, B0.w)
                H2_( 8, A0.z, B0.x) H2_( 9, A0.z, B0.y) H2_(10, A0.w, B0.x) H2_(11, A0.w, B0.y)
                H2_(12, A0.z, B0.z) H2_(13, A0.z, B0.w) H2_(14, A0.w, B0.z) H2_(15, A0.w, B0.w)
                H2_(16, A1.x, B1.x) H2_(17, A1.x, B1.y) H2_(18, A1.y, B1.x) H2_(19, A1.y, B1.y)
                H2_(20, A1.x, B1.z) H2_(21, A1.x, B1.w) H2_(22, A1.y, B1.z) H2_(23, A1.y, B1.w)
                H2_(24, A1.z, B1.x) H2_(25, A1.z, B1.y) H2_(26, A1.w, B1.x) H2_(27, A1.w, B1.y)
                H2_(28, A1.z, B1.z) H2_(29, A1.z, B1.w) H2_(30, A1.w, B1.z) H2_(31, A1.w, B1.w)
            } else {
                H2_(0, pa0, B0.x) H2_(1, pa0, B0.y) H2_(2, pa1, B0.x) H2_(3, pa1, B0.y)
                H2_(4, pa0, B0.z) H2_(5, pa0, B0.w) H2_(6, pa1, B0.z) H2_(7, pa1, B0.w)
            }
            #undef H2_
        }
        __syncwarp();

        // warp scan of 128-bin histogram; locate critical bin
        uint4 hv = *(const uint4*)&HistW[lane*4];
        int h0 = (int)hv.x, h1 = (int)hv.y, h2 = (int)hv.z, h3 = (int)hv.w;
        int ssum = h0 + h1 + h2 + h3;
        int incl = ssum;
        #pragma unroll
        for (int off = 1; off < 32; off <<= 1) {
            int v = __shfl_up_sync(FULLM, incl, off);
            if (lane >= off) incl += v;
        }
        int excl = incl - ssum;
        int target = 63 - c_sel;
        bool has = (excl <= target && target < incl);
        int cum = excl, bsel = lane*4;
        if (target >= cum + h0) { cum += h0; bsel++;
            if (target >= cum + h1) { cum += h1; bsel++;
                if (target >= cum + h2) { cum += h2; bsel++; } } }
        int infoL = (bsel << 16) | cum;
        unsigned bal = __ballot_sync(FULLM, has);
        int info = __shfl_sync(FULLM, infoL, bal ? (__ffs(bal) - 1) : 31);
        if (!bal) info = 127 << 16;

        int cb = info >> 16;
        c_sel += info & 0xffff;
        int mcrit = (int)HistW[cb];

        // classification via float thresholds (exact-equivalent to int bins)
        float cbF   = (float)cb;
        float cbHiF = (cb == 127) ? 3.0e38f : (float)(cb + 1);
        #define CLS_(k, pa, pb) if ((actm >> (k)) & 1u) { \
            float x = fmaxf((((pa) + (pb)) - lo) * scale, 0.f); \
            if (x < cbF)         { selm |= 1u << (k); actm &= ~(1u << (k)); } \
            else if (x >= cbHiF) { actm &= ~(1u << (k)); } }
        if (FULL_L) {
            CLS_( 0, A0.x, B0.x) CLS_( 1, A0.x, B0.y) CLS_( 2, A0.y, B0.x) CLS_( 3, A0.y, B0.y)
            CLS_( 4, A0.x, B0.z) CLS_( 5, A0.x, B0.w) CLS_( 6, A0.y, B0.z) CLS_( 7, A0.y, B0.w)
            CLS_( 8, A0.z, B0.x) CLS_( 9, A0.z, B0.y) CLS_(10, A0.w, B0.x) CLS_(11, A0.w, B0.y)
            CLS_(12, A0.z, B0.z) CLS_(13, A0.z, B0.w) CLS_(14, A0.w, B0.z) CLS_(15, A0.w, B0.w)
            CLS_(16, A1.x, B1.x) CLS_(17, A1.x, B1.y) CLS_(18, A1.y, B1.x) CLS_(19, A1.y, B1.y)
            CLS_(20, A1.x, B1.z) CLS_(21, A1.x, B1.w) CLS_(22, A1.y, B1.z) CLS_(23, A1.y, B1.w)
            CLS_(24, A1.z, B1.x) CLS_(25, A1.z, B1.y) CLS_(26, A1.w, B1.x) CLS_(27, A1.w, B1.y)
            CLS_(28, A1.z, B1.z) CLS_(29, A1.z, B1.w) CLS_(30, A1.w, B1.z) CLS_(31, A1.w, B1.w)
        } else {
            CLS_(0, pa0, B0.x) CLS_(1, pa0, B0.y) CLS_(2, pa1, B0.x) CLS_(3, pa1, B0.y)
            CLS_(4, pa0, B0.z) CLS_(5, pa0, B0.w) CLS_(6, pa1, B0.z) CLS_(7, pa1, B0.w)
        }
        #undef CLS_
        if (mcrit <= 64 || lev == 3) break;
        float w = (hi - lo) * 0.0078125f;
        float nlo = fmaf((float)cb, w, lo);
        hi = nlo + w;
        lo = nlo;
    }

    // ---- compaction: popc-prefix slots (same order as serial cursor) ----
    {
        int nsel = __popc(selm), neq = __popc(actm);
        int packed = nsel | (neq << 16);
        int incl = packed;
        #pragma unroll
        for (int off = 1; off < 32; off <<= 1) {
            int v = __shfl_up_sync(FULLM, incl, off);
            if (lane >= off) incl += v;
        }
        int excl = incl - packed;
        int sb = excl & 0xffff;
        int eb = excl >> 16;
        const int q8 = (lane & 1) << 3;   // layer-6 q offset

        #define CMP_(k, pa, pb, qv, ps, idxv) { \
            if ((selm >> (k)) & 1u) { \
                int pos = sb + __popc(selm & ((1u << (k)) - 1u)); \
                if (pos < 64) { \
                    CdistW[nxt][pos] = (pa) + (pb); \
                    CsymW[nxt][pos]  = (ps) | ((unsigned)(qv) << shl); } \
            } else if ((actm >> (k)) & 1u) { \
                int pos = eb + __popc(actm & ((1u << (k)) - 1u)); \
                if (pos < 128) \
                    EqKW[pos] = (((unsigned long long)__float_as_uint((pa) + (pb))) << 10) \
                              | (unsigned)(idxv); } }
        if (FULL_L) {
            CMP_( 0, A0.x, B0.x,  0, psym0, 32*lane+ 0) CMP_( 1, A0.x, B0.y,  1, psym0, 32*lane+ 1)
            CMP_( 2, A0.y, B0.x,  2, psym0, 32*lane+ 2) CMP_( 3, A0.y, B0.y,  3, psym0, 32*lane+ 3)
            CMP_( 4, A0.x, B0.z,  4, psym0, 32*lane+ 4) CMP_( 5, A0.x, B0.w,  5, psym0, 32*lane+ 5)
            CMP_( 6, A0.y, B0.z,  6, psym0, 32*lane+ 6) CMP_( 7, A0.y, B0.w,  7, psym0, 32*lane+ 7)
            CMP_( 8, A0.z, B0.x,  8, psym0, 32*lane+ 8) CMP_( 9, A0.z, B0.y,  9, psym0, 32*lane+ 9)
            CMP_(10, A0.w, B0.x, 10, psym0, 32*lane+10) CMP_(11, A0.w, B0.y, 11, psym0, 32*lane+11)
            CMP_(12, A0.z, B0.z, 12, psym0, 32*lane+12) CMP_(13, A0.z, B0.w, 13, psym0, 32*lane+13)
            CMP_(14, A0.w, B0.z, 14, psym0, 32*lane+14) CMP_(15, A0.w, B0.w, 15, psym0, 32*lane+15)
            CMP_(16, A1.x, B1.x,  0, psym1, 32*lane+16) CMP_(17, A1.x, B1.y,  1, psym1, 32*lane+17)
            CMP_(18, A1.y, B1.x,  2, psym1, 32*lane+18) CMP_(19, A1.y, B1.y,  3, psym1, 32*lane+19)
            CMP_(20, A1.x, B1.z,  4, psym1, 32*lane+20) CMP_(21, A1.x, B1.w,  5, psym1, 32*lane+21)
            CMP_(22, A1.y, B1.z,  6, psym1, 32*lane+22) CMP_(23, A1.y, B1.w,  7, psym1, 32*lane+23)
            CMP_(24, A1.z, B1.x,  8, psym1, 32*lane+24) CMP_(25, A1.z, B1.y,  9, psym1, 32*lane+25)
            CMP_(26, A1.w, B1.x, 10, psym1, 32*lane+26) CMP_(27, A1.w, B1.y, 11, psym1, 32*lane+27)
            CMP_(28, A1.z, B1.z, 12, psym1, 32*lane+28) CMP_(29, A1.z, B1.w, 13, psym1, 32*lane+29)
            CMP_(30, A1.w, B1.z, 14, psym1, 32*lane+30) CMP_(31, A1.w, B1.w, 15, psym1, 32*lane+31)
        } else {
            CMP_(0, pa0, B0.x, q8 + 0, psym0, 8*lane + 0) CMP_(1, pa0, B0.y, q8 + 1, psym0, 8*lane + 1)
            CMP_(2, pa1, B0.x, q8 + 2, psym0, 8*lane + 2) CMP_(3, pa1, B0.y, q8 + 3, psym0, 8*lane + 3)
            CMP_(4, pa0, B0.z, q8 + 4, psym0, 8*lane + 4) CMP_(5, pa0, B0.w, q8 + 5, psym0, 8*lane + 5)
            CMP_(6, pa1, B0.z, q8 + 6, psym0, 8*lane + 6) CMP_(7, pa1, B0.w, q8 + 7, psym0, 8*lane + 7)
        }
        #undef CMP_
        __syncwarp();

        // exact tie ranking on the critical bin
        int eqTot = __shfl_sync(FULLM, incl, 31) >> 16;
        int mm = eqTot < 128 ? eqTot : 128;
        int need = 64 - c_sel;
        for (int e = lane; e < mm; e += 32) {
            unsigned long long mykey = EqKW[e];
            int rank = 0;
            for (int j = 0; j < mm; j++) rank += (EqKW[j] < mykey);
            if (rank < need) {
                int s = c_sel + rank;
                if (s < 64) {
                    int idx = (int)(mykey & 1023ull);
                    int p = idx >> 4, q = idx & 15;
                    CdistW[nxt][s] = __uint_as_float((unsigned)(mykey >> 10));
                    CsymW[nxt][s]  = CsymW[cur][p] | ((unsigned)q << shl);
                }
            }
        }
    }
    __syncwarp();
}

__global__ void __launch_bounds__(64, 16) kbest_kernel(
    const float* __restrict__ g_yr, const float* __restrict__ g_yi,
    const float* __restrict__ g_hr, const float* __restrict__ g_hi,
    const float* __restrict__ g_sr, const float* __restrict__ g_si,
    const float* __restrict__ g_pr, const float* __restrict__ g_pi,
    float* __restrict__ g_out)
{
    const int lane = threadIdx.x & 31;
    const int wrp  = threadIdx.x >> 5;
    const int b    = blockIdx.x * WPB + wrp;

    __shared__ __align__(16) char Buf[WPB][PHASE_BYTES];
    __shared__ float2 Csh[WPB][8][8];
    __shared__ float2 Ybar[WPB][8];
    __shared__ int    Order[WPB][8];
    __shared__ float2 Pts[WPB][16];
    __shared__ float    Cdist[WPB][2][64];
    __shared__ unsigned Csym[WPB][2][64];

    char* bufW = Buf[wrp];
    // phase A overlays
    float2 (*LshW)[17] = (float2(*)[17])bufW;                      // 2176
    float2 (*HtsW)[9]  = (float2(*)[9])(bufW + 2176);              // 1152
    // phase B overlays
    float (*PrsW)[4] = (float(*)[4])bufW;                          // 1024 (layer-6 only)
    float (*PisW)[4] = (float(*)[4])(bufW + 1024);                 // 1024 (layer-6 only)
    unsigned *HistW  = (unsigned*)(bufW + 2048);                   // 512
    unsigned long long *EqKW = (unsigned long long*)(bufW + 2560); // 1024

    float2 (*CshW)[8]  = Csh[wrp];
    float2 *YbarW = Ybar[wrp];
    int    *OrderW = Order[wrp];
    float2 *PtsW  = Pts[wrp];
    float    (*CdistW)[64] = Cdist[wrp];
    unsigned (*CsymW)[64]  = Csym[wrp];

    // ---------------- load ----------------
    for (int t = lane; t < 256; t += 32)
        LshW[t >> 4][t & 15] = make_float2(g_sr[b*256 + t], g_si[b*256 + t]);
    for (int t = lane; t < 128; t += 32)
        HtsW[t >> 3][t & 7] = make_float2(g_hr[b*128 + t], g_hi[b*128 + t]);
    if (lane < 16) {
        HtsW[lane][8] = make_float2(g_yr[b*16 + lane], g_yi[b*16 + lane]);
        PtsW[lane]    = make_float2(g_pr[lane], g_pi[lane]);
    }
    __syncwarp();

    // ------- Cholesky 16x16 complex (round-9 exact form) -------
    #pragma unroll 1
    for (int jc = 0; jc < 16; jc++) {
        float sx = 0.f, sy = 0.f;
        if (lane >= jc && lane < 16) {
            float2 a0 = LshW[lane][jc];
            sx = a0.x; sy = a0.y;
            for (int k = 0; k < jc; k++) {       // s -= L[i,k]*conj(L[jc,k])
                float2 a = LshW[lane][k], c = LshW[jc][k];
                sx -= a.x*c.x + a.y*c.y;
                sy -= a.y*c.x - a.x*c.y;
            }
        }
        float dj = __shfl_sync(FULLM, sx, jc);
        float dl = sqrtf(dj);
        if (lane == jc) LshW[lane][jc] = make_float2(dl, 0.f);
        else if (lane > jc && lane < 16) LshW[lane][jc] = make_float2(sx/dl, sy/dl);
        __syncwarp();
    }

    // ------- forward solve L X = [h | y]: two columns per pass -------
    #pragma unroll 1
    for (int cp = 0; cp < 5; cp++) {
        int c = cp*2 + (lane >> 4);
        bool valid = (c < 9);
        int r = lane & 15;
        #pragma unroll 1
        for (int i = 0; i < 16; i++) {
            float xr = 0.f, xi = 0.f;
            if (r == i && valid) {
                float2 v = HtsW[i][c];
                float dd = LshW[i][i].x;
                xr = v.x / dd; xi = v.y / dd;
                HtsW[i][c] = make_float2(xr, xi);
            }
            xr = __shfl_sync(FULLM, xr, i, 16);
            xi = __shfl_sync(FULLM, xi, i, 16);
            if (r > i && valid) {
                float2 lij = LshW[r][i];
                float2 v = HtsW[r][c];
                v.x -= lij.x*xr - lij.y*xi;
                v.y -= lij.x*xi + lij.y*xr;
                HtsW[r][c] = v;
            }
            __syncwarp();
        }
    }

    // ------- column norms (round-9 exact form: sequential 16 terms) -------
    if (lane < 8) {
        float nr = 0.f;
        #pragma unroll
        for (int m = 0; m < 16; m++) {
            float2 a = HtsW[m][lane];
            nr += a.x*a.x + a.y*a.y;
        }
        CdistW[1][lane] = nr;   // Cdist[1] free pre-layer-loop
    }
    __syncwarp();
    if (lane < 8) {
        float ni = CdistW[1][lane];
        int rank = 0;
        #pragma unroll
        for (int j = 0; j < 8; j++) {
            float nj = CdistW[1][j];
            rank += (nj > ni) || (nj == ni && j < lane);
        }
        OrderW[rank] = lane;
    }
    __syncwarp();

    // ------- permuted Gram: lower triangle + Ybar, directly -------
    if (lane < 8) CshW[lane][lane] = make_float2(CdistW[1][OrderW[lane]], 0.f);
    for (int t = lane; t < 36; t += 32) {
        int i, j, oi, oj;
        if (t < 28) {                 // strict lower: row i (1..7) has i entries
            int tt = t; i = 1;
            while (tt >= i) { tt -= i; i++; }
            j = tt;
            oi = OrderW[i]; oj = OrderW[j];
        } else {                      // Ybar[i] = conj-dot(col Order[i], y)
            i = t - 28; j = -1;
            oi = OrderW[i]; oj = 8;
        }
        float gx = 0.f, gy = 0.f;
        #pragma unroll
        for (int m = 0; m < 16; m++) {
            float2 a = HtsW[m][oi], c = HtsW[m][oj];
            gx += a.x*c.x + a.y*c.y;
            gy += a.x*c.y - a.y*c.x;
        }
        if (t < 28) CshW[i][j] = make_float2(gx, gy);
        else        YbarW[i]   = make_float2(gx, gy);
    }
    __syncwarp();
    // ---- phase A buffers (Lsh, Hts) are DEAD from here on ----

    // ------- Cholesky 8x8 (round-9 exact form) -------
    #pragma unroll 1
    for (int jc = 0; jc < 8; jc++) {
        float sx = 0.f, sy = 0.f;
        if (lane >= jc && lane < 8) {
            float2 a0 = CshW[lane][jc]; sx = a0.x; sy = a0.y;
            for (int k = 0; k < jc; k++) {
                float2 a = CshW[lane][k], c = CshW[jc][k];
                sx -= a.x*c.x + a.y*c.y;
                sy -= a.y*c.x - a.x*c.y;
            }
        }
        float dj = __shfl_sync(FULLM, sx, jc);
        float dl = sqrtf(dj);
        if (lane == jc) CshW[lane][jc] = make_float2(dl, 0.f);
        else if (lane > jc && lane < 8) CshW[lane][jc] = make_float2(sx/dl, sy/dl);
        __syncwarp();
    }
    // ------- solve C ybar = z_p -------
    #pragma unroll 1
    for (int i = 0; i < 8; i++) {
        float xr = 0.f, xi = 0.f;
        if (lane == i) {
            float2 v = YbarW[i];
            float dd = CshW[i][i].x;
            xr = v.x / dd; xi = v.y / dd;
            YbarW[i] = make_float2(xr, xi);
        }
        xr = __shfl_sync(FULLM, xr, i);
        xi = __shfl_sync(FULLM, xi, i);
        if (lane > i && lane < 8) {
            float2 lij = CshW[lane][i];
            float2 v = YbarW[lane];
            v.x -= lij.x*xr - lij.y*xi;
            v.y -= lij.x*xi + lij.y*xr;
            YbarW[lane] = v;
        }
        __syncwarp();
    }

    // ---------------- layer 7: 16 initial candidates ----------------
    int cur = 0;
    if (lane < 16) {
        float r77 = CshW[7][7].x;
        float2 p = PtsW[lane];
        float rr = YbarW[7].x - r77*p.x;
        float ri = YbarW[7].y - r77*p.y;
        CdistW[0][lane] = rr*rr + ri*ri;
        CsymW[0][lane]  = (unsigned)lane << 28;
    }
    __syncwarp();

    // ---------------- layers 6..0 ----------------
    layer_step<false>(6, cur, lane, CshW, YbarW, PtsW, CdistW, CsymW,
                      PrsW, PisW, HistW, EqKW);
    cur ^= 1;
    #pragma unroll 1
    for (int l = 5; l >= 0; l--) {
        layer_step<true>(l, cur, lane, CshW, YbarW, PtsW, CdistW, CsymW,
                         PrsW, PisW, HistW, EqKW);
        cur ^= 1;
    }

    // ---------------- LLR: one (layer, bit) pair per lane ----------------
    {
        int l = lane >> 2, j = lane & 3;
        float d0 = 1000000000.0f, d1 = 1000000000.0f;
        #pragma unroll 4
        for (int k = 0; k < 64; k++) {
            float d = CdistW[cur][k];
            int q = (int)((CsymW[cur][k] >> (4*l)) & 15u);
            if ((q >> (3 - j)) & 1) d1 = fminf(d1, d);
            else                    d0 = fminf(d0, d);
        }
        float llr = fminf(fmaxf(d0 - d1, -20.f), 20.f);
        g_out[b*32 + OrderW[l]*4 + j] = llr;
    }
}

extern "C" void kernel_launch(void* const* d_in, const int* in_sizes, int n_in,
                              void* d_out, int out_size)
{
    const float* yr = (const float*)d_in[0];
    const float* yi = (const float*)d_in[1];
    const float* hr = (const float*)d_in[2];
    const float* hi = (const float*)d_in[3];
    const float* sr = (const float*)d_in[4];
    const float* si = (const float*)d_in[5];
    const float* pr = (const float*)d_in[6];
    const float* pi = (const float*)d_in[7];
    int B = in_sizes[0] / 16;
    kbest_kernel<<<B / WPB, 32 * WPB>>>(yr, yi, hr, hi, sr, si, pr, pi, (float*)d_out);
}

// round 14
// speedup vs baseline: 1.2048x; 1.2048x over previous
#include <cuda_runtime.h>

// KBestDetector: B=16384, M=16 rx, S=8 streams, 16-QAM (NBPS=4), K=64.
// WARP-PER-BATCH, CTA = 2 warps. No __syncthreads; warp-synchronous.
//
// FROZEN (round-10 lesson): chol16 / chol8 / column norms keep round-9's
// exact summation order — the argsort and K-best tree are discretely
// sensitive to preamble rounding.
// FROZEN (round-12 lesson): classification/compaction stay as compact
// __ffs walks — full 32-way unrolling blows past I$ L0 and stalls issue.
//
// Round-13 change: __launch_bounds__(64, 18) (56-reg cap) to lift the
// RF-bound occupancy ceiling from 32 to 36 warps/SM.

#define FULLM 0xffffffffu
#define WPB 2
#define PHASE_BYTES 3584

__global__ void __launch_bounds__(64, 18) kbest_kernel(
    const float* __restrict__ g_yr, const float* __restrict__ g_yi,
    const float* __restrict__ g_hr, const float* __restrict__ g_hi,
    const float* __restrict__ g_sr, const float* __restrict__ g_si,
    const float* __restrict__ g_pr, const float* __restrict__ g_pi,
    float* __restrict__ g_out)
{
    const int lane = threadIdx.x & 31;
    const int wrp  = threadIdx.x >> 5;
    const int b    = blockIdx.x * WPB + wrp;

    __shared__ __align__(16) char Buf[WPB][PHASE_BYTES];
    __shared__ float2 Csh[WPB][8][8];
    __shared__ float2 Ybar[WPB][8];
    __shared__ int    Order[WPB][8];
    __shared__ float2 Pts[WPB][16];
    __shared__ float    Cdist[WPB][2][64];
    __shared__ unsigned Csym[WPB][2][64];

    char* bufW = Buf[wrp];
    // phase A overlays
    float2 (*LshW)[17] = (float2(*)[17])bufW;                      // 2176
    float2 (*HtsW)[9]  = (float2(*)[9])(bufW + 2176);              // 1152
    // phase B overlays
    float (*PrsW)[4] = (float(*)[4])bufW;                          // 1024
    float (*PisW)[4] = (float(*)[4])(bufW + 1024);                 // 1024
    unsigned *HistW  = (unsigned*)(bufW + 2048);                   // 512
    unsigned long long *EqKW = (unsigned long long*)(bufW + 2560); // 1024

    float2 (*CshW)[8]  = Csh[wrp];
    float2 *YbarW = Ybar[wrp];
    int    *OrderW = Order[wrp];
    float2 *PtsW  = Pts[wrp];
    float    (*CdistW)[64] = Cdist[wrp];
    unsigned (*CsymW)[64]  = Csym[wrp];

    // ---------------- load ----------------
    for (int t = lane; t < 256; t += 32)
        LshW[t >> 4][t & 15] = make_float2(g_sr[b*256 + t], g_si[b*256 + t]);
    for (int t = lane; t < 128; t += 32)
        HtsW[t >> 3][t & 7] = make_float2(g_hr[b*128 + t], g_hi[b*128 + t]);
    if (lane < 16) {
        HtsW[lane][8] = make_float2(g_yr[b*16 + lane], g_yi[b*16 + lane]);
        PtsW[lane]    = make_float2(g_pr[lane], g_pi[lane]);
    }
    __syncwarp();

    // ------- Cholesky 16x16 complex (round-9 exact form) -------
    #pragma unroll 1
    for (int jc = 0; jc < 16; jc++) {
        float sx = 0.f, sy = 0.f;
        if (lane >= jc && lane < 16) {
            float2 a0 = LshW[lane][jc];
            sx = a0.x; sy = a0.y;
            for (int k = 0; k < jc; k++) {       // s -= L[i,k]*conj(L[jc,k])
                float2 a = LshW[lane][k], c = LshW[jc][k];
                sx -= a.x*c.x + a.y*c.y;
                sy -= a.y*c.x - a.x*c.y;
            }
        }
        float dj = __shfl_sync(FULLM, sx, jc);
        float dl = sqrtf(dj);
        if (lane == jc) LshW[lane][jc] = make_float2(dl, 0.f);
        else if (lane > jc && lane < 16) LshW[lane][jc] = make_float2(sx/dl, sy/dl);
        __syncwarp();
    }

    // ------- forward solve L X = [h | y]: two columns per pass -------
    #pragma unroll 1
    for (int cp = 0; cp < 5; cp++) {
        int c = cp*2 + (lane >> 4);
        bool valid = (c < 9);
        int r = lane & 15;
        #pragma unroll 1
        for (int i = 0; i < 16; i++) {
            float xr = 0.f, xi = 0.f;
            if (r == i && valid) {
                float2 v = HtsW[i][c];
                float dd = LshW[i][i].x;
                xr = v.x / dd; xi = v.y / dd;
                HtsW[i][c] = make_float2(xr, xi);
            }
            xr = __shfl_sync(FULLM, xr, i, 16);
            xi = __shfl_sync(FULLM, xi, i, 16);
            if (r > i && valid) {
                float2 lij = LshW[r][i];
                float2 v = HtsW[r][c];
                v.x -= lij.x*xr - lij.y*xi;
                v.y -= lij.x*xi + lij.y*xr;
                HtsW[r][c] = v;
            }
            __syncwarp();
        }
    }

    // ------- column norms (round-9 exact form: sequential 16 terms) -------
    if (lane < 8) {
        float nr = 0.f;
        #pragma unroll
        for (int m = 0; m < 16; m++) {
            float2 a = HtsW[m][lane];
            nr += a.x*a.x + a.y*a.y;
        }
        CdistW[1][lane] = nr;   // Cdist[1] free pre-layer-loop
    }
    __syncwarp();
    if (lane < 8) {
        float ni = CdistW[1][lane];
        int rank = 0;
        #pragma unroll
        for (int j = 0; j < 8; j++) {
            float nj = CdistW[1][j];
            rank += (nj > ni) || (nj == ni && j < lane);
        }
        OrderW[rank] = lane;
    }
    __syncwarp();

    // ------- permuted Gram: lower triangle + Ybar, directly -------
    if (lane < 8) CshW[lane][lane] = make_float2(CdistW[1][OrderW[lane]], 0.f);
    for (int t = lane; t < 36; t += 32) {
        int i, j, oi, oj;
        if (t < 28) {                 // strict lower: row i (1..7) has i entries
            int tt = t; i = 1;
            while (tt >= i) { tt -= i; i++; }
            j = tt;
            oi = OrderW[i]; oj = OrderW[j];
        } else {                      // Ybar[i] = conj-dot(col Order[i], y)
            i = t - 28; j = -1;
            oi = OrderW[i]; oj = 8;
        }
        float gx = 0.f, gy = 0.f;
        #pragma unroll
        for (int m = 0; m < 16; m++) {
            float2 a = HtsW[m][oi], c = HtsW[m][oj];
            gx += a.x*c.x + a.y*c.y;
            gy += a.x*c.y - a.y*c.x;
        }
        if (t < 28) CshW[i][j] = make_float2(gx, gy);
        else        YbarW[i]   = make_float2(gx, gy);
    }
    __syncwarp();
    // ---- phase A buffers (Lsh, Hts) are DEAD from here on ----

    // ------- Cholesky 8x8 (round-9 exact form) -------
    #pragma unroll 1
    for (int jc = 0; jc < 8; jc++) {
        float sx = 0.f, sy = 0.f;
        if (lane >= jc && lane < 8) {
            float2 a0 = CshW[lane][jc]; sx = a0.x; sy = a0.y;
            for (int k = 0; k < jc; k++) {
                float2 a = CshW[lane][k], c = CshW[jc][k];
                sx -= a.x*c.x + a.y*c.y;
                sy -= a.y*c.x - a.x*c.y;
            }
        }
        float dj = __shfl_sync(FULLM, sx, jc);
        float dl = sqrtf(dj);
        if (lane == jc) CshW[lane][jc] = make_float2(dl, 0.f);
        else if (lane > jc && lane < 8) CshW[lane][jc] = make_float2(sx/dl, sy/dl);
        __syncwarp();
    }
    // ------- solve C ybar = z_p -------
    #pragma unroll 1
    for (int i = 0; i < 8; i++) {
        float xr = 0.f, xi = 0.f;
        if (lane == i) {
            float2 v = YbarW[i];
            float dd = CshW[i][i].x;
            xr = v.x / dd; xi = v.y / dd;
            YbarW[i] = make_float2(xr, xi);
        }
        xr = __shfl_sync(FULLM, xr, i);
        xi = __shfl_sync(FULLM, xi, i);
        if (lane > i && lane < 8) {
            float2 lij = CshW[lane][i];
            float2 v = YbarW[lane];
            v.x -= lij.x*xr - lij.y*xi;
            v.y -= lij.x*xi + lij.y*xr;
            YbarW[lane] = v;
        }
        __syncwarp();
    }

    // ---------------- layer 7: 16 initial candidates ----------------
    int cur = 0;
    if (lane < 16) {
        float r77 = CshW[7][7].x;
        float2 p = PtsW[lane];
        float rr = YbarW[7].x - r77*p.x;
        float ri = YbarW[7].y - r77*p.y;
        CdistW[0][lane] = rr*rr + ri*ri;
        CsymW[0][lane]  = (unsigned)lane << 28;
    }
    __syncwarp();

    // ---------------- layers 6..0 ----------------
    for (int l = 6; l >= 0; l--) {
        const bool full = (l != 6);
        const int nP  = full ? 64 : 16;
        const int nxt = cur ^ 1;

        // per-parent separable distance tables
        for (int p = lane; p < nP; p += 32) {
            unsigned sym = CsymW[cur][p];
            float pd = CdistW[cur][p];
            float ir = 0.f, ii = 0.f;
            for (int j = l + 1; j < 8; j++) {
                int q = (sym >> (4*j)) & 15;
                float2 c = CshW[j][l];
                float2 pt = PtsW[q];
                ir += c.x*pt.x + c.y*pt.y;
                ii += c.x*pt.y - c.y*pt.x;
            }
            float br = YbarW[l].x - ir;
            float bi = YbarW[l].y - ii;
            float rll = CshW[l][l].x;
            float4 prv, piv;
            {
                float t0 = fmaf(-rll, PtsW[0].x,  br);
                float t1 = fmaf(-rll, PtsW[2].x,  br);
                float t2 = fmaf(-rll, PtsW[8].x,  br);
                float t3 = fmaf(-rll, PtsW[10].x, br);
                prv.x = fmaf(t0, t0, pd); prv.y = fmaf(t1, t1, pd);
                prv.z = fmaf(t2, t2, pd); prv.w = fmaf(t3, t3, pd);
            }
            {
                float t0 = fmaf(-rll, PtsW[0].y, bi);
                float t1 = fmaf(-rll, PtsW[1].y, bi);
                float t2 = fmaf(-rll, PtsW[4].y, bi);
                float t3 = fmaf(-rll, PtsW[5].y, bi);
                piv.x = t0*t0; piv.y = t1*t1; piv.z = t2*t2; piv.w = t3*t3;
            }
            *(float4*)PrsW[p] = prv;
            *(float4*)PisW[p] = piv;
        }
        *(uint4*)&HistW[lane*4] = make_uint4(0u, 0u, 0u, 0u);
        __syncwarp();

        // pass 1: per-lane min + certificate payload
        float mn, Tpay;
        float4 A0, B0, A1, B1;
        float pa0 = 0.f, pa1 = 0.f;
        if (full) {
            A0 = *(const float4*)PrsW[2*lane];     B0 = *(const float4*)PisW[2*lane];
            A1 = *(const float4*)PrsW[2*lane + 1]; B1 = *(const float4*)PisW[2*lane + 1];
            #define MIN4_(pa, B) fminf(fminf(pa + B.x, pa + B.y), fminf(pa + B.z, pa + B.w))
            float m0 = fminf(fminf(MIN4_(A0.x, B0), MIN4_(A0.y, B0)),
                             fminf(MIN4_(A0.z, B0), MIN4_(A0.w, B0)));
            float m1 = fminf(fminf(MIN4_(A1.x, B1), MIN4_(A1.y, B1)),
                             fminf(MIN4_(A1.z, B1), MIN4_(A1.w, B1)));
            mn   = fminf(m0, m1);
            Tpay = fmaxf(m0, m1);          // parent-best: certifies d_(64)
        } else {
            A0 = *(const float4*)PrsW[lane >> 1];
            B0 = *(const float4*)PisW[lane >> 1];
            pa0 = (lane & 1) ? A0.z : A0.x;
            pa1 = (lane & 1) ? A0.w : A0.y;
            float d0 = pa0 + B0.x, d1 = pa0 + B0.y, d2 = pa1 + B0.x, d3 = pa1 + B0.y;
            float d4 = pa0 + B0.z, d5 = pa0 + B0.w, d6 = pa1 + B0.z, d7 = pa1 + B0.w;
            mn   = fminf(fminf(fminf(d0,d1),fminf(d2,d3)), fminf(fminf(d4,d5),fminf(d6,d7)));
            Tpay = fmaxf(fmaxf(fmaxf(d0,d1),fmaxf(d2,d3)), fmaxf(fmaxf(d4,d5),fmaxf(d6,d7)));
        }
        float lo = mn, T = Tpay;
        #pragma unroll
        for (int o = 16; o; o >>= 1) {
            lo = fminf(lo, __shfl_xor_sync(FULLM, lo, o));
            T  = fmaxf(T,  __shfl_xor_sync(FULLM, T,  o));
        }
        float hi = T;
        float scale = 128.f / fmaxf(hi - lo, 1e-30f);

        // pass 2: prune (d<=T) + level-0 histogram + active mask
        unsigned actm = 0u, selm = 0u;
        #define P2_(k, pa, pb) { float d = (pa) + (pb); \
            if (d <= T) { int bn = (int)((d - lo) * scale); \
                bn = bn > 127 ? 127 : bn; \
                atomicAdd(&HistW[bn], 1u); actm |= (1u << (k)); } }
        if (full) {
            P2_( 0, A0.x, B0.x) P2_( 1, A0.x, B0.y) P2_( 2, A0.y, B0.x) P2_( 3, A0.y, B0.y)
            P2_( 4, A0.x, B0.z) P2_( 5, A0.x, B0.w) P2_( 6, A0.y, B0.z) P2_( 7, A0.y, B0.w)
            P2_( 8, A0.z, B0.x) P2_( 9, A0.z, B0.y) P2_(10, A0.w, B0.x) P2_(11, A0.w, B0.y)
            P2_(12, A0.z, B0.z) P2_(13, A0.z, B0.w) P2_(14, A0.w, B0.z) P2_(15, A0.w, B0.w)
            P2_(16, A1.x, B1.x) P2_(17, A1.x, B1.y) P2_(18, A1.y, B1.x) P2_(19, A1.y, B1.y)
            P2_(20, A1.x, B1.z) P2_(21, A1.x, B1.w) P2_(22, A1.y, B1.z) P2_(23, A1.y, B1.w)
            P2_(24, A1.z, B1.x) P2_(25, A1.z, B1.y) P2_(26, A1.w, B1.x) P2_(27, A1.w, B1.y)
            P2_(28, A1.z, B1.z) P2_(29, A1.z, B1.w) P2_(30, A1.w, B1.z) P2_(31, A1.w, B1.w)
        } else {
            P2_(0, pa0, B0.x) P2_(1, pa0, B0.y) P2_(2, pa1, B0.x) P2_(3, pa1, B0.y)
            P2_(4, pa0, B0.z) P2_(5, pa0, B0.w) P2_(6, pa1, B0.z) P2_(7, pa1, B0.w)
        }
        #undef P2_

        // adaptive select loop (exact; ties via EqK)
        int c_sel = 0;
        #pragma unroll 1
        for (int lev = 0; ; lev++) {
            if (lev) {
                __syncwarp();
                *(uint4*)&HistW[lane*4] = make_uint4(0u, 0u, 0u, 0u);
                __syncwarp();
                scale = 128.f / fmaxf(hi - lo, 1e-30f);
                unsigned m = actm;
                while (m) {
                    int k = __ffs(m) - 1; m &= m - 1;
                    int p, q;
                    if (full) { p = (lane << 1) + (k >> 4); q = k & 15; }
                    else      { p = lane >> 1; q = ((lane & 1) << 3) | k; }
                    int a  = ((q >> 2) & 2) | ((q >> 1) & 1);
                    int bq = ((q >> 1) & 2) | (q & 1);
                    float d = PrsW[p][a] + PisW[p][bq];
                    int bn = (int)((d - lo) * scale);
                    bn = bn < 0 ? 0 : (bn > 127 ? 127 : bn);
                    atomicAdd(&HistW[bn], 1u);
                }
            }
            __syncwarp();

            // warp scan of 128-bin histogram; locate critical bin
            uint4 hv = *(const uint4*)&HistW[lane*4];
            int h0 = (int)hv.x, h1 = (int)hv.y, h2 = (int)hv.z, h3 = (int)hv.w;
            int ssum = h0 + h1 + h2 + h3;
            int incl = ssum;
            #pragma unroll
            for (int off = 1; off < 32; off <<= 1) {
                int v = __shfl_up_sync(FULLM, incl, off);
                if (lane >= off) incl += v;
            }
            int excl = incl - ssum;
            int target = 63 - c_sel;
            bool has = (excl <= target && target < incl);
            int cum = excl, bsel = lane*4;
            if (target >= cum + h0) { cum += h0; bsel++;
                if (target >= cum + h1) { cum += h1; bsel++;
                    if (target >= cum + h2) { cum += h2; bsel++; } } }
            int infoL = (bsel << 16) | cum;
            unsigned bal = __ballot_sync(FULLM, has);
            int info = __shfl_sync(FULLM, infoL, bal ? (__ffs(bal) - 1) : 31);
            if (!bal) info = 127 << 16;

            int cb = info >> 16;
            c_sel += info & 0xffff;
            int mcrit = (int)HistW[cb];

            // classification via float thresholds (exact-equivalent to int bins)
            float cbF   = (float)cb;
            float cbHiF = (cb == 127) ? 3.0e38f : (float)(cb + 1);
            unsigned m = actm;
            while (m) {
                int k = __ffs(m) - 1; m &= m - 1;
                int p, q;
                if (full) { p = (lane << 1) + (k >> 4); q = k & 15; }
                else      { p = lane >> 1; q = ((lane & 1) << 3) | k; }
                int a  = ((q >> 2) & 2) | ((q >> 1) & 1);
                int bq = ((q >> 1) & 2) | (q & 1);
                float d = PrsW[p][a] + PisW[p][bq];
                float x = fmaxf((d - lo) * scale, 0.f);
                if (x < cbF)         { selm |= 1u << k; actm &= ~(1u << k); }
                else if (x >= cbHiF) { actm &= ~(1u << k); }
            }
            if (mcrit <= 64 || lev == 3) break;
            float w = (hi - lo) * 0.0078125f;
            float nlo = fmaf((float)cb, w, lo);
            hi = nlo + w;
            lo = nlo;
        }

        // scan-based compaction (single warp owns counters: no atomics)
        {
            int nsel = __popc(selm), neq = __popc(actm);
            int packed = nsel | (neq << 16);
            int incl = packed;
            #pragma unroll
            for (int off = 1; off < 32; off <<= 1) {
                int v = __shfl_up_sync(FULLM, incl, off);
                if (lane >= off) incl += v;
            }
            int excl = incl - packed;
            int sb = excl & 0xffff;
            int eb = excl >> 16;

            unsigned m = selm;
            while (m) {
                int k = __ffs(m) - 1; m &= m - 1;
                int p, q;
                if (full) { p = (lane << 1) + (k >> 4); q = k & 15; }
                else      { p = lane >> 1; q = ((lane & 1) << 3) | k; }
                int a  = ((q >> 2) & 2) | ((q >> 1) & 1);
                int bq = ((q >> 1) & 2) | (q & 1);
                float d = PrsW[p][a] + PisW[p][bq];
                if (sb < 64) {
                    CdistW[nxt][sb] = d;
                    CsymW[nxt][sb]  = CsymW[cur][p] | ((unsigned)q << (4*l));
                }
                sb++;
            }
            m = actm;
            while (m) {
                int k = __ffs(m) - 1; m &= m - 1;
                int p, q;
                if (full) { p = (lane << 1) + (k >> 4); q = k & 15; }
                else      { p = lane >> 1; q = ((lane & 1) << 3) | k; }
                int a  = ((q >> 2) & 2) | ((q >> 1) & 1);
                int bq = ((q >> 1) & 2) | (q & 1);
                float d = PrsW[p][a] + PisW[p][bq];
                int idx = p*16 + q;          // reference tie-break index
                if (eb < 128)
                    EqKW[eb] = (((unsigned long long)__float_as_uint(d)) << 10)
                             | (unsigned)idx;
                eb++;
            }
            __syncwarp();

            // exact tie ranking on the critical bin
            int eqTot = __shfl_sync(FULLM, incl, 31) >> 16;
            int mm = eqTot < 128 ? eqTot : 128;
            int need = 64 - c_sel;
            for (int e = lane; e < mm; e += 32) {
                unsigned long long mykey = EqKW[e];
                int rank = 0;
                for (int j = 0; j < mm; j++) rank += (EqKW[j] < mykey);
                if (rank < need) {
                    int s = c_sel + rank;
                    if (s < 64) {
                        int idx = (int)(mykey & 1023ull);
                        int p = idx >> 4, q = idx & 15;
                        CdistW[nxt][s] = __uint_as_float((unsigned)(mykey >> 10));
                        CsymW[nxt][s]  = CsymW[cur][p] | ((unsigned)q << (4*l));
                    }
                }
            }
        }
        __syncwarp();
        cur = nxt;
    }

    // ---------------- LLR: one (layer, bit) pair per lane ----------------
    {
        int l = lane >> 2, j = lane & 3;
        float d0 = 1000000000.0f, d1 = 1000000000.0f;
        #pragma unroll 4
        for (int k = 0; k < 64; k++) {
            float d = CdistW[cur][k];
            int q = (int)((CsymW[cur][k] >> (4*l)) & 15u);
            if ((q >> (3 - j)) & 1) d1 = fminf(d1, d);
            else                    d0 = fminf(d0, d);
        }
        float llr = fminf(fmaxf(d0 - d1, -20.f), 20.f);
        g_out[b*32 + OrderW[l]*4 + j] = llr;
    }
}

extern "C" void kernel_launch(void* const* d_in, const int* in_sizes, int n_in,
                              void* d_out, int out_size)
{
    const float* yr = (const float*)d_in[0];
    const float* yi = (const float*)d_in[1];
    const float* hr = (const float*)d_in[2];
    const float* hi = (const float*)d_in[3];
    const float* sr = (const float*)d_in[4];
    const float* si = (const float*)d_in[5];
    const float* pr = (const float*)d_in[6];
    const float* pi = (const float*)d_in[7];
    int B = in_sizes[0] / 16;
    kbest_kernel<<<B / WPB, 32 * WPB>>>(yr, yi, hr, hi, sr, si, pr, pi, (float*)d_out);
}